// round 1
// baseline (speedup 1.0000x reference)
#include <cuda_runtime.h>
#include <cuda_bf16.h>

// Haar DWT (pywt 'haar', torch-style flipped filters + cross-correlation):
//   a=x[h,w] b=x[h,w+1] c=x[h+1,w] d=x[h+1,w+1]  (zero pad right/bottom)
//   LL=.5(a+b+c+d)  LH=.5(a+b-c-d)  HL=.5(a-b+c-d)  HH=.5(a-b-c+d)
// out[b, 4c+k, h, w]  ->  plane index 4*(b*C+c)+k

#define DWT_W 256
#define DWT_H 256
#define ROWS_PER_THREAD 8
// block: (64, 4) -> 64 float4 columns cover W=256; 4 y-groups x 8 rows = 32 rows/block
// grid:  (H/32 = 8, B*C)

__global__ __launch_bounds__(256, 4)
void haar_dwt_kernel(const float* __restrict__ x, float* __restrict__ out)
{
    const int tx = threadIdx.x;            // float4 column, 0..63
    const int ty = threadIdx.y;            // 0..3
    const int bc = blockIdx.y;             // b*C + c
    const int h0 = blockIdx.x * (4 * ROWS_PER_THREAD) + ty * ROWS_PER_THREAD;

    const int W4 = DWT_W / 4;
    const float*  xp  = x + (size_t)bc * DWT_H * DWT_W;
    const float4* xp4 = (const float4*)xp;

    const int w = 4 * tx;

    // output plane bases (float4 granularity)
    float4* o0 = (float4*)out + (size_t)(4 * bc + 0) * DWT_H * W4;
    float4* o1 = (float4*)out + (size_t)(4 * bc + 1) * DWT_H * W4;
    float4* o2 = (float4*)out + (size_t)(4 * bc + 2) * DWT_H * W4;
    float4* o3 = (float4*)out + (size_t)(4 * bc + 3) * DWT_H * W4;

    // top row (register-carried)
    float4 top  = xp4[h0 * W4 + tx];
    float  topn = (tx < W4 - 1) ? __ldg(&xp[h0 * DWT_W + w + 4]) : 0.0f;

#pragma unroll
    for (int r = 0; r < ROWS_PER_THREAD; r++) {
        const int h = h0 + r;
        float4 bot;
        float  botn;
        if (h + 1 < DWT_H) {
            bot  = xp4[(h + 1) * W4 + tx];
            botn = (tx < W4 - 1) ? __ldg(&xp[(h + 1) * DWT_W + w + 4]) : 0.0f;
        } else {
            bot  = make_float4(0.f, 0.f, 0.f, 0.f);
            botn = 0.0f;
        }

        const float t0 = top.x, t1 = top.y, t2 = top.z, t3 = top.w, t4 = topn;
        const float b0 = bot.x, b1 = bot.y, b2 = bot.z, b3 = bot.w, b4 = botn;

        float4 LL, LH, HL, HH;
        {
            float s1 = t0 + t1, s2 = b0 + b1, d1 = t0 - t1, d2 = b0 - b1;
            LL.x = 0.5f * (s1 + s2); LH.x = 0.5f * (s1 - s2);
            HL.x = 0.5f * (d1 + d2); HH.x = 0.5f * (d1 - d2);
        }
        {
            float s1 = t1 + t2, s2 = b1 + b2, d1 = t1 - t2, d2 = b1 - b2;
            LL.y = 0.5f * (s1 + s2); LH.y = 0.5f * (s1 - s2);
            HL.y = 0.5f * (d1 + d2); HH.y = 0.5f * (d1 - d2);
        }
        {
            float s1 = t2 + t3, s2 = b2 + b3, d1 = t2 - t3, d2 = b2 - b3;
            LL.z = 0.5f * (s1 + s2); LH.z = 0.5f * (s1 - s2);
            HL.z = 0.5f * (d1 + d2); HH.z = 0.5f * (d1 - d2);
        }
        {
            float s1 = t3 + t4, s2 = b3 + b4, d1 = t3 - t4, d2 = b3 - b4;
            LL.w = 0.5f * (s1 + s2); LH.w = 0.5f * (s1 - s2);
            HL.w = 0.5f * (d1 + d2); HH.w = 0.5f * (d1 - d2);
        }

        const size_t oidx = (size_t)h * W4 + tx;
        __stcs(o0 + oidx, LL);
        __stcs(o1 + oidx, LH);
        __stcs(o2 + oidx, HL);
        __stcs(o3 + oidx, HH);

        top  = bot;
        topn = botn;
    }
}

extern "C" void kernel_launch(void* const* d_in, const int* in_sizes, int n_in,
                              void* d_out, int out_size)
{
    const float* x = (const float*)d_in[0];
    float* out = (float*)d_out;

    const int n_planes = in_sizes[0] / (DWT_H * DWT_W);   // B*C = 512

    dim3 block(64, 4, 1);
    dim3 grid(DWT_H / (4 * ROWS_PER_THREAD), n_planes, 1);
    haar_dwt_kernel<<<grid, block>>>(x, out);
}

// round 2
// speedup vs baseline: 1.0468x; 1.0468x over previous
#include <cuda_runtime.h>
#include <cuda_bf16.h>

// Haar DWT (pywt 'haar', torch-style flipped filters + cross-correlation):
//   a=x[h,w] b=x[h,w+1] c=x[h+1,w] d=x[h+1,w+1]  (zero pad right/bottom)
//   LL=.5(a+b+c+d)  LH=.5(a+b-c-d)  HL=.5(a-b+c-d)  HH=.5(a-b-c+d)
// out[b, 4c+k, h, w]  ->  plane index 4*(b*C+c)+k
//
// R2: no row-carry. One output row per thread, 4 front-batched loads (MLP=4),
// max occupancy (2048 thr/SM). Input rows read twice but second read is an
// L1/L2 hit (vertical neighbor rows handled inside the same block).

#define DWT_W 256
#define DWT_H 256

// block: (64, 4) -> 64 float4 columns cover W=256; 4 rows per block
// grid:  (H/4 = 64, B*C = 512)

__global__ __launch_bounds__(256, 8)
void haar_dwt_kernel(const float* __restrict__ x, float* __restrict__ out)
{
    const int tx = threadIdx.x;            // float4 column, 0..63
    const int h  = blockIdx.x * 4 + threadIdx.y;   // output row
    const int bc = blockIdx.y;             // b*C + c

    const int W4 = DWT_W / 4;
    const float*  xp  = x + (size_t)bc * DWT_H * DWT_W;
    const float4* xp4 = (const float4*)xp;

    const int w = 4 * tx;
    const bool has_right = (tx < W4 - 1);
    const bool has_bot   = (h < DWT_H - 1);

    // ---- front-batched independent loads (MLP = 4) ----
    float4 top = xp4[h * W4 + tx];
    float4 bot = has_bot ? xp4[(h + 1) * W4 + tx] : make_float4(0.f, 0.f, 0.f, 0.f);
    float topn = has_right ? __ldg(&xp[h * DWT_W + w + 4]) : 0.0f;
    float botn = (has_right && has_bot) ? __ldg(&xp[(h + 1) * DWT_W + w + 4]) : 0.0f;

    const float t0 = top.x, t1 = top.y, t2 = top.z, t3 = top.w, t4 = topn;
    const float b0 = bot.x, b1 = bot.y, b2 = bot.z, b3 = bot.w, b4 = botn;

    // horizontal sums/diffs (shared by all 4 subbands)
    const float ts0 = t0 + t1, ts1 = t1 + t2, ts2 = t2 + t3, ts3 = t3 + t4;
    const float td0 = t0 - t1, td1 = t1 - t2, td2 = t2 - t3, td3 = t3 - t4;
    const float bs0 = b0 + b1, bs1 = b1 + b2, bs2 = b2 + b3, bs3 = b3 + b4;
    const float bd0 = b0 - b1, bd1 = b1 - b2, bd2 = b2 - b3, bd3 = b3 - b4;

    float4* ob = (float4*)out + (size_t)(4 * bc) * DWT_H * W4;
    const size_t oidx = (size_t)h * W4 + tx;
    const size_t plane4 = (size_t)DWT_H * W4;

    // compute one subband at a time to keep register live-set small
    float4 v;

    // LL
    v.x = 0.5f * (ts0 + bs0); v.y = 0.5f * (ts1 + bs1);
    v.z = 0.5f * (ts2 + bs2); v.w = 0.5f * (ts3 + bs3);
    __stcs(ob + oidx, v);

    // LH
    v.x = 0.5f * (ts0 - bs0); v.y = 0.5f * (ts1 - bs1);
    v.z = 0.5f * (ts2 - bs2); v.w = 0.5f * (ts3 - bs3);
    __stcs(ob + plane4 + oidx, v);

    // HL
    v.x = 0.5f * (td0 + bd0); v.y = 0.5f * (td1 + bd1);
    v.z = 0.5f * (td2 + bd2); v.w = 0.5f * (td3 + bd3);
    __stcs(ob + 2 * plane4 + oidx, v);

    // HH
    v.x = 0.5f * (td0 - bd0); v.y = 0.5f * (td1 - bd1);
    v.z = 0.5f * (td2 - bd2); v.w = 0.5f * (td3 - bd3);
    __stcs(ob + 3 * plane4 + oidx, v);
}

extern "C" void kernel_launch(void* const* d_in, const int* in_sizes, int n_in,
                              void* d_out, int out_size)
{
    const float* x = (const float*)d_in[0];
    float* out = (float*)d_out;

    const int n_planes = in_sizes[0] / (DWT_H * DWT_W);   // B*C = 512

    dim3 block(64, 4, 1);
    dim3 grid(DWT_H / 4, n_planes, 1);
    haar_dwt_kernel<<<grid, block>>>(x, out);
}

// round 3
// speedup vs baseline: 1.0557x; 1.0085x over previous
#include <cuda_runtime.h>
#include <cuda_bf16.h>

// Haar DWT (pywt 'haar', torch-style flipped filters + cross-correlation):
//   a=x[h,w] b=x[h,w+1] c=x[h+1,w] d=x[h+1,w+1]  (zero pad right/bottom)
//   LL=.5(a+b+c+d)  LH=.5(a+b-c-d)  HL=.5(a-b+c-d)  HH=.5(a-b-c+d)
// out[b, 4c+k, h, w]  ->  plane index 4*(b*C+c)+k
//
// R3: warp-per-row, dual column-group. Each lane owns float4 at w=4*lane and
// w=4*lane+128. All horizontal neighbors come from warp shuffles -> zero
// scalar LDGs; every load/store is a perfect 512B/warp transaction.
// 4 front-batched LDG.128 per thread (MLP=4), 8 STG.128.

#define DWT_W 256
#define DWT_H 256
#define W4    (DWT_W / 4)
#define PLANE4 ((size_t)DWT_H * W4)
#define FULL  0xffffffffu

__device__ __forceinline__ void subbands_store(
    float4* __restrict__ ob, size_t oidx,
    float4 T, float4 B, float tn, float bn)
{
    // horizontal sums/diffs
    const float ts0 = T.x + T.y, ts1 = T.y + T.z, ts2 = T.z + T.w, ts3 = T.w + tn;
    const float td0 = T.x - T.y, td1 = T.y - T.z, td2 = T.z - T.w, td3 = T.w - tn;
    const float bs0 = B.x + B.y, bs1 = B.y + B.z, bs2 = B.z + B.w, bs3 = B.w + bn;
    const float bd0 = B.x - B.y, bd1 = B.y - B.z, bd2 = B.z - B.w, bd3 = B.w - bn;

    float4 v;
    v.x = 0.5f * (ts0 + bs0); v.y = 0.5f * (ts1 + bs1);
    v.z = 0.5f * (ts2 + bs2); v.w = 0.5f * (ts3 + bs3);
    __stcs(ob + oidx, v);                                   // LL

    v.x = 0.5f * (ts0 - bs0); v.y = 0.5f * (ts1 - bs1);
    v.z = 0.5f * (ts2 - bs2); v.w = 0.5f * (ts3 - bs3);
    __stcs(ob + PLANE4 + oidx, v);                          // LH

    v.x = 0.5f * (td0 + bd0); v.y = 0.5f * (td1 + bd1);
    v.z = 0.5f * (td2 + bd2); v.w = 0.5f * (td3 + bd3);
    __stcs(ob + 2 * PLANE4 + oidx, v);                      // HL

    v.x = 0.5f * (td0 - bd0); v.y = 0.5f * (td1 - bd1);
    v.z = 0.5f * (td2 - bd2); v.w = 0.5f * (td3 - bd3);
    __stcs(ob + 3 * PLANE4 + oidx, v);                      // HH
}

// block (32, 8): one warp per row, 8 rows per block. grid: (H/8, B*C)
__global__ __launch_bounds__(256)
void haar_dwt_kernel(const float* __restrict__ x, float* __restrict__ out)
{
    const int lane = threadIdx.x;                 // 0..31
    const int h    = blockIdx.x * 8 + threadIdx.y;
    const int bc   = blockIdx.y;

    const float4* xp4 = (const float4*)(x + (size_t)bc * DWT_H * DWT_W);
    const float4* rt  = xp4 + h * W4;

    // ---- front-batched loads: 4 independent 512B/warp LDG.128 ----
    float4 t1 = rt[lane];            // cols [4*lane, 4*lane+4)
    float4 t2 = rt[lane + 32];       // cols [4*lane+128, ...)
    float4 u1, u2;
    if (h < DWT_H - 1) {
        const float4* ru = rt + W4;
        u1 = ru[lane];
        u2 = ru[lane + 32];
    } else {
        u1 = make_float4(0.f, 0.f, 0.f, 0.f);
        u2 = u1;
    }

    // ---- horizontal neighbors via shuffle (no extra LDGs) ----
    float nt1 = __shfl_down_sync(FULL, t1.x, 1);   // lane l: col 4l+4
    float nu1 = __shfl_down_sync(FULL, u1.x, 1);
    float nt2 = __shfl_down_sync(FULL, t2.x, 1);   // lane l: col 4l+132
    float nu2 = __shfl_down_sync(FULL, u2.x, 1);
    const float t2x0 = __shfl_sync(FULL, t2.x, 0); // col 128 (for g1 lane 31)
    const float u2x0 = __shfl_sync(FULL, u2.x, 0);
    if (lane == 31) {
        nt1 = t2x0;            // col 128
        nu1 = u2x0;
        nt2 = 0.f;             // col 256 -> zero pad
        nu2 = 0.f;
    }

    float4* ob = (float4*)out + (size_t)(4 * bc) * PLANE4;
    const size_t o1 = (size_t)h * W4 + lane;

    subbands_store(ob, o1,      t1, u1, nt1, nu1);   // group 1: cols [0,128)
    subbands_store(ob, o1 + 32, t2, u2, nt2, nu2);   // group 2: cols [128,256)
}

extern "C" void kernel_launch(void* const* d_in, const int* in_sizes, int n_in,
                              void* d_out, int out_size)
{
    const float* x = (const float*)d_in[0];
    float* out = (float*)d_out;

    const int n_planes = in_sizes[0] / (DWT_H * DWT_W);   // B*C = 512

    dim3 block(32, 8, 1);
    dim3 grid(DWT_H / 8, n_planes, 1);
    haar_dwt_kernel<<<grid, block>>>(x, out);
}